// round 15
// baseline (speedup 1.0000x reference)
#include <cuda_runtime.h>
#include <cuda_fp16.h>
#include <math.h>

#define NROWS 8192
#define DDIM  128
#define KNEG  100
#define RSEL  160          // candidate superset rank (slack for tf32+fp16 key noise)
#define CAP   320          // candidate buffer capacity
#define INV_TEMP (1.0f/0.07f)
#define TPAD 132
#define MPAD 136           // half-precision mirror staging stride
#define GEMM_SMEM (2 * 128 * TPAD * 4)
#define NTILE 64
#define NTRI  (NTILE * (NTILE + 1) / 2)   // 2080 upper-triangular tiles
#define HPAD 257           // histogram copy stride

// ---------------- scratch (device globals: allowed). 16B-aligned for vector ld/st ----
__device__ __align__(16) float  g_x1t[NROWS * DDIM];          // transposed x1 (8192 x 128)
__device__ __align__(16) float  g_x2t[NROWS * DDIM];          // transposed x2
__device__ float g_sq [NROWS];                                // |x1_i|^2
__device__ float g_invn[NROWS];                               // 1/|x1_i|
__device__ float g_pos[NROWS];                                // positive sums
__device__ __align__(16) __half g_key[(size_t)NROWS * NROWS]; // fp16 selection keys (128 MB)
__device__ float g_loss[NROWS];

// ---------------- K0: transpose (b,d,h,w) -> (b*h*w, d); both tensors in one launch ----
__global__ void transpose_kernel(const float* __restrict__ x1, const float* __restrict__ x2) {
    __shared__ float tile[32][33];
    int which = blockIdx.z & 1, b = blockIdx.z >> 1;
    const float* x = which ? x2 : x1;
    float* xt = which ? g_x2t : g_x1t;
    int dt = blockIdx.y, pt = blockIdx.x;
    int tx = threadIdx.x, ty = threadIdx.y;            // 32 x 8
    const float* src = x + (size_t)b * 131072 + (size_t)(dt * 32) * 1024 + pt * 32;
    #pragma unroll
    for (int r = ty; r < 32; r += 8)
        tile[r][tx] = src[(size_t)r * 1024 + tx];
    __syncthreads();
    float* dst = xt + (size_t)(b * 1024 + pt * 32) * DDIM + dt * 32;
    #pragma unroll
    for (int r = ty; r < 32; r += 8)
        dst[(size_t)r * DDIM + tx] = tile[tx][r];
}

// ---------------- K1: per-row norms + positive term (exact fp32) ----------------
__global__ void stats_kernel() {
    int warp = threadIdx.x >> 5, lane = threadIdx.x & 31;
    int row = blockIdx.x * 8 + warp;
    const float4* r1 = (const float4*)(g_x1t + (size_t)row * DDIM);
    const float4* r2 = (const float4*)(g_x2t + (size_t)row * DDIM);
    float4 a = r1[lane], b = r2[lane];
    float s1 = a.x*a.x + a.y*a.y + a.z*a.z + a.w*a.w;
    float s2 = b.x*b.x + b.y*b.y + b.z*b.z + b.w*b.w;
    #pragma unroll
    for (int o = 16; o > 0; o >>= 1) {
        s1 += __shfl_xor_sync(0xffffffffu, s1, o);
        s2 += __shfl_xor_sync(0xffffffffu, s2, o);
    }
    float in1 = 1.0f / fmaxf(sqrtf(s1), 1e-12f);
    float in2 = 1.0f / fmaxf(sqrtf(s2), 1e-12f);
    float sc = in1 * in2 * INV_TEMP;
    float p = expf(a.x*b.x*sc) + expf(a.y*b.y*sc) + expf(a.z*b.z*sc) + expf(a.w*b.w*sc);
    #pragma unroll
    for (int o = 16; o > 0; o >>= 1) p += __shfl_xor_sync(0xffffffffu, p, o);
    if (lane == 0) { g_sq[row] = s1; g_invn[row] = in1; g_pos[row] = p; }
}

// ---------------- K2: tf32 mma Gram, upper-triangle; epilogue emits fp16 KEYS ----------------
__device__ __forceinline__ void mma_tf32(float c[4], const unsigned a[4], const unsigned b[2]) {
    asm volatile(
        "mma.sync.aligned.m16n8k8.row.col.f32.tf32.tf32.f32 "
        "{%0,%1,%2,%3}, {%4,%5,%6,%7}, {%8,%9}, {%0,%1,%2,%3};\n"
        : "+f"(c[0]), "+f"(c[1]), "+f"(c[2]), "+f"(c[3])
        : "r"(a[0]), "r"(a[1]), "r"(a[2]), "r"(a[3]), "r"(b[0]), "r"(b[1]));
}

__global__ __launch_bounds__(512, 1) void gemm_tc_kernel() {
    extern __shared__ float sm[];
    float* As = sm;                      // [128][TPAD]
    float* Bs = sm + 128 * TPAD;
    __shared__ float sqA[128], sqB[128];
    const float* A = g_x1t;

    int t = blockIdx.x;
    int bi = 0;
    while (t >= NTILE - bi) { t -= NTILE - bi; bi++; }
    int bj = bi + t;
    int bm = bi * 128, bn = bj * 128;

    int tid = threadIdx.x;
    int wid = tid >> 5, lane = tid & 31;
    int wm = wid >> 2, wn = wid & 3;
    int g = lane >> 2, tg = lane & 3;

    if (tid < 128) sqA[tid] = g_sq[bm + tid];
    else if (tid < 256) sqB[tid - 128] = g_sq[bn + tid - 128];

    unsigned sA = (unsigned)__cvta_generic_to_shared(As);
    unsigned sB = (unsigned)__cvta_generic_to_shared(Bs);

    #pragma unroll
    for (int c = 0; c < 4; c++) {
        int k0 = c * 32;
        #pragma unroll
        for (int tt = 0; tt < 2; tt++) {
            int idx = tid + tt * 512;
            int r  = idx >> 3;
            int kk = (idx & 7) << 2;
            const float* ga = A + (size_t)(bm + r) * DDIM + k0 + kk;
            unsigned da = sA + (unsigned)(r * TPAD + k0 + kk) * 4u;
            asm volatile("cp.async.ca.shared.global [%0], [%1], 16;" :: "r"(da), "l"(ga));
            const float* gb = A + (size_t)(bn + r) * DDIM + k0 + kk;
            unsigned db = sB + (unsigned)(r * TPAD + k0 + kk) * 4u;
            asm volatile("cp.async.ca.shared.global [%0], [%1], 16;" :: "r"(db), "l"(gb));
        }
        asm volatile("cp.async.commit_group;");
    }

    float acc[2][4][4];
    #pragma unroll
    for (int mt = 0; mt < 2; mt++)
        #pragma unroll
        for (int nt = 0; nt < 4; nt++)
            #pragma unroll
            for (int q = 0; q < 4; q++) acc[mt][nt][q] = 0.0f;

    #pragma unroll
    for (int ch = 0; ch < 4; ch++) {
        if      (ch == 0) asm volatile("cp.async.wait_group 3;");
        else if (ch == 1) asm volatile("cp.async.wait_group 2;");
        else if (ch == 2) asm volatile("cp.async.wait_group 1;");
        else              asm volatile("cp.async.wait_group 0;");
        __syncthreads();
        #pragma unroll
        for (int kk = 0; kk < 4; kk++) {
            int kb = ch * 32 + kk * 8;
            unsigned a[2][4], b[4][2];
            #pragma unroll
            for (int mt = 0; mt < 2; mt++) {
                int r0 = wm * 32 + mt * 16;
                a[mt][0] = __float_as_uint(As[(r0 + g    ) * TPAD + kb + tg]);
                a[mt][1] = __float_as_uint(As[(r0 + g + 8) * TPAD + kb + tg]);
                a[mt][2] = __float_as_uint(As[(r0 + g    ) * TPAD + kb + tg + 4]);
                a[mt][3] = __float_as_uint(As[(r0 + g + 8) * TPAD + kb + tg + 4]);
            }
            #pragma unroll
            for (int nt = 0; nt < 4; nt++) {
                int rb = wn * 32 + nt * 8 + g;
                b[nt][0] = __float_as_uint(Bs[rb * TPAD + kb + tg]);
                b[nt][1] = __float_as_uint(Bs[rb * TPAD + kb + tg + 4]);
            }
            #pragma unroll
            for (int mt = 0; mt < 2; mt++)
                #pragma unroll
                for (int nt = 0; nt < 4; nt++)
                    mma_tf32(acc[mt][nt], a[mt], b[nt]);
        }
    }

    // direct tile (bm, bn): key = sq[col] - 2*dot, fp16
    #pragma unroll
    for (int mt = 0; mt < 2; mt++) {
        #pragma unroll
        for (int nt = 0; nt < 4; nt++) {
            int lr = wm * 32 + mt * 16 + g;
            int lc = wn * 32 + nt * 8 + tg * 2;
            float k0 = sqB[lc]     - 2.0f * acc[mt][nt][0];
            float k1 = sqB[lc + 1] - 2.0f * acc[mt][nt][1];
            float k2 = sqB[lc]     - 2.0f * acc[mt][nt][2];
            float k3 = sqB[lc + 1] - 2.0f * acc[mt][nt][3];
            *(__half2*)(g_key + (size_t)(bm + lr) * NROWS + bn + lc) =
                __floats2half2_rn(k0, k1);
            *(__half2*)(g_key + (size_t)(bm + lr + 8) * NROWS + bn + lc) =
                __floats2half2_rn(k2, k3);
        }
    }

    // mirrored tile (bn, bm)
    if (bi != bj) {
        __syncthreads();
        __half* Cth = (__half*)sm;       // [128 rows (bn-local)][MPAD]
        #pragma unroll
        for (int mt = 0; mt < 2; mt++) {
            #pragma unroll
            for (int nt = 0; nt < 4; nt++) {
                int r = wm * 32 + mt * 16 + g;
                int c = wn * 32 + nt * 8 + tg * 2;
                Cth[(c    ) * MPAD + r    ] = __float2half_rn(sqA[r]     - 2.0f * acc[mt][nt][0]);
                Cth[(c + 1) * MPAD + r    ] = __float2half_rn(sqA[r]     - 2.0f * acc[mt][nt][1]);
                Cth[(c    ) * MPAD + r + 8] = __float2half_rn(sqA[r + 8] - 2.0f * acc[mt][nt][2]);
                Cth[(c + 1) * MPAD + r + 8] = __float2half_rn(sqA[r + 8] - 2.0f * acc[mt][nt][3]);
            }
        }
        __syncthreads();
        #pragma unroll
        for (int it = 0; it < 4; it++) {
            int idx8 = it * 512 + tid;
            int rT = idx8 >> 4, c8 = (idx8 & 15) << 3;
            uint4 v = *(const uint4*)(Cth + rT * MPAD + c8);
            *(uint4*)(g_key + (size_t)(bn + rT) * NROWS + bm + c8) = v;
        }
    }
}

// ---------------- K3: 16-bit radix candidate select + exact fp32 re-rank ----------------
// key[l] (l = v*8 + s) corresponds to column j = tid*8 + v*2048 + s.
__device__ __forceinline__ int key_index(int tid, int l) {
    return tid * 8 + ((l >> 3) << 11) + (l & 7);
}
__device__ __forceinline__ unsigned ord16(unsigned h) {   // order-preserving fp16->u16
    return (h & 0x8000u) ? (~h & 0xFFFFu) : (h | 0x8000u);
}

__global__ __launch_bounds__(256, 4) void select_kernel() {
    int i = blockIdx.x;
    int tid = threadIdx.x, lane = tid & 31, wid = tid >> 5;
    const uint4* krow = (const uint4*)(g_key + (size_t)i * NROWS);  // 1024 uint4

    __shared__ unsigned hist16c[16][HPAD];       // lane-parity split: copy = wid*2 + (lane&1)
    __shared__ unsigned s_wsum[8];
    __shared__ unsigned s_bin, s_above, s_n;
    __shared__ __align__(16) float srow[DDIM];
    __shared__ int      s_cand[CAP];
    __shared__ __align__(16) float s_keyv[CAP + 4];
    __shared__ float    s_dotc[CAP];
    __shared__ float    sacc[8];

    if (tid < 32)
        ((float4*)srow)[tid] = ((const float4*)(g_x1t + (size_t)i * DDIM))[tid];

    unsigned key[32];                                    // ordered u16 keys
    #pragma unroll
    for (int v = 0; v < 4; v++) {
        uint4 q = krow[tid + v * 256];
        unsigned w[4] = { q.x, q.y, q.z, q.w };
        #pragma unroll
        for (int wi = 0; wi < 4; wi++) {
            key[v * 8 + wi * 2    ] = ord16(w[wi] & 0xFFFFu);
            key[v * 8 + wi * 2 + 1] = ord16(w[wi] >> 16);
        }
    }

    // ---- 2-pass radix select (16 hist copies): exact RSEL-th largest u16 key ----
    unsigned mask = 0u, val = 0u;
    unsigned rank = RSEL;
    #pragma unroll
    for (int pass = 0; pass < 2; pass++) {
        int shift = 8 - pass * 8;
        #pragma unroll
        for (int w = 0; w < 16; w++) hist16c[w][tid] = 0u;
        __syncthreads();
        unsigned* myhist = hist16c[wid * 2 + (lane & 1)];
        #pragma unroll
        for (int l = 0; l < 32; l++) {
            unsigned k = key[l];
            if ((k & mask) == val)
                atomicAdd(&myhist[(k >> shift) & 255u], 1u);
        }
        __syncthreads();
        unsigned c = 0;                          // thread t owns bin (255-t); merge 16 copies
        #pragma unroll
        for (int w = 0; w < 16; w++) c += hist16c[w][255 - tid];
        unsigned v = c;
        #pragma unroll
        for (int o = 1; o < 32; o <<= 1) {
            unsigned u = __shfl_up_sync(0xffffffffu, v, o);
            if (lane >= o) v += u;
        }
        if (lane == 31) s_wsum[wid] = v;
        __syncthreads();
        unsigned off = 0;
        for (int w = 0; w < wid; w++) off += s_wsum[w];
        v += off;
        if (v >= rank && (v - c) < rank) {       // unique boundary thread
            s_bin = (unsigned)(255 - tid);
            s_above = v - c;
        }
        __syncthreads();
        val  |= s_bin << shift;
        mask |= 0xFFu << shift;
        rank -= s_above;
        __syncthreads();
    }
    unsigned thr = val;

    // ---- deterministic compaction of candidate indices (scan, no atomics) ----
    unsigned myc = 0;
    #pragma unroll
    for (int l = 0; l < 32; l++) myc += (key[l] >= thr);
    unsigned v = myc;
    #pragma unroll
    for (int o = 1; o < 32; o <<= 1) {
        unsigned u = __shfl_up_sync(0xffffffffu, v, o);
        if (lane >= o) v += u;
    }
    if (lane == 31) s_wsum[wid] = v;
    __syncthreads();
    unsigned off = 0;
    for (int w = 0; w < wid; w++) off += s_wsum[w];
    unsigned p = off + v - myc;                  // exclusive prefix
    #pragma unroll
    for (int l = 0; l < 32; l++) {
        if (key[l] >= thr) {
            if (p < CAP) s_cand[p] = key_index(tid, l);
            p++;
        }
    }
    if (tid == 255) s_n = (p < CAP) ? p : CAP;
    __syncthreads();
    int n = (int)s_n;

    // ---- exact fp32 dots (thread per candidate) + pad key tail for vector re-rank ----
    for (int c = tid; c < n; c += 256) {
        int j = s_cand[c];
        const float4* xr = (const float4*)(g_x1t + (size_t)j * DDIM);
        float p0 = 0.f, p1 = 0.f, p2 = 0.f, p3 = 0.f;
        #pragma unroll 8
        for (int q = 0; q < 32; q++) {
            float4 b4 = xr[q];
            float4 a4 = ((const float4*)srow)[q];
            p0 += a4.x * b4.x; p1 += a4.y * b4.y;
            p2 += a4.z * b4.z; p3 += a4.w * b4.w;
        }
        float d = (p0 + p1) + (p2 + p3);
        s_dotc[c] = d;
        s_keyv[c] = g_sq[j] - 2.0f * d;          // exact fp32 key
    }
    for (int c = n + tid; c < CAP + 4; c += 256)
        s_keyv[c] = -3.4e38f;                    // pad so float4 re-rank reads are inert
    __syncthreads();

    // ---- exact re-rank among candidates (vectorized, strict >); sum exp over top-100 ----
    float inv_i = g_invn[i];
    float acc = 0.0f;
    int n4 = (n + 3) >> 2;
    for (int c = tid; c < n; c += 256) {
        float kc = s_keyv[c];
        int greater = 0;
        for (int f4 = 0; f4 < n4; f4++) {
            float4 kf = ((const float4*)s_keyv)[f4];
            greater += (kf.x > kc) + (kf.y > kc) + (kf.z > kc) + (kf.w > kc);
        }
        if (greater < KNEG)
            acc += expf(s_dotc[c] * inv_i * g_invn[s_cand[c]] * INV_TEMP);
    }
    #pragma unroll
    for (int o = 16; o > 0; o >>= 1) acc += __shfl_xor_sync(0xffffffffu, acc, o);
    if (lane == 0) sacc[wid] = acc;
    __syncthreads();
    if (tid == 0) {
        float t = 0.0f;
        for (int w = 0; w < 8; w++) t += sacc[w];
        g_loss[i] = log1pf(t / g_pos[i]);        // log(P+N) - log(P)
    }
}

// ---------------- K4: deterministic mean ----------------
__global__ void reduce_kernel(float* __restrict__ out) {
    __shared__ float s[256];
    float a = 0.0f;
    for (int j = threadIdx.x; j < NROWS; j += 256) a += g_loss[j];
    s[threadIdx.x] = a;
    __syncthreads();
    for (int st = 128; st > 0; st >>= 1) {
        if (threadIdx.x < st) s[threadIdx.x] += s[threadIdx.x + st];
        __syncthreads();
    }
    if (threadIdx.x == 0) out[0] = s[0] * (1.0f / NROWS);
}

// ---------------- launch ----------------
extern "C" void kernel_launch(void* const* d_in, const int* in_sizes, int n_in,
                              void* d_out, int out_size) {
    const float* x1 = (const float*)d_in[0];
    const float* x2 = (const float*)d_in[1];
    float* out = (float*)d_out;

    cudaFuncSetAttribute(gemm_tc_kernel,
                         cudaFuncAttributeMaxDynamicSharedMemorySize, GEMM_SMEM);

    dim3 tgrid(32, 4, 16), tblk(32, 8);      // z = batch*2 + which
    transpose_kernel<<<tgrid, tblk>>>(x1, x2);
    stats_kernel<<<NROWS / 8, 256>>>();
    gemm_tc_kernel<<<NTRI, 512, GEMM_SMEM>>>();
    select_kernel<<<NROWS, 256>>>();
    reduce_kernel<<<1, 256>>>(out);
}

// round 16
// speedup vs baseline: 1.0460x; 1.0460x over previous
#include <cuda_runtime.h>
#include <cuda_fp16.h>
#include <math.h>

#define NROWS 8192
#define DDIM  128
#define KNEG  100
#define RSEL  160          // candidate superset rank (slack for tf32+fp16 key noise)
#define CAP   320          // candidate buffer capacity
#define INV_TEMP (1.0f/0.07f)
#define TPAD 132
#define MPAD 136           // half-precision mirror staging stride
#define GEMM_SMEM (2 * 128 * TPAD * 4)
#define NTILE 64
#define NTRI  (NTILE * (NTILE + 1) / 2)   // 2080 upper-triangular tiles
#define HPAD 257           // histogram copy stride
#define NHIST 32           // histogram copies (atomic conflict dilution)

// ---------------- scratch (device globals: allowed). 16B-aligned for vector ld/st ----
__device__ __align__(16) float  g_x1t[NROWS * DDIM];          // transposed x1 (8192 x 128)
__device__ __align__(16) float  g_x2t[NROWS * DDIM];          // transposed x2
__device__ float g_sq [NROWS];                                // |x1_i|^2
__device__ float g_invn[NROWS];                               // 1/|x1_i|
__device__ float g_pos[NROWS];                                // positive sums
__device__ __align__(16) __half g_key[(size_t)NROWS * NROWS]; // fp16 selection keys (128 MB)
__device__ float g_loss[NROWS];

// ---------------- K0: transpose (b,d,h,w) -> (b*h*w, d); both tensors in one launch ----
__global__ void transpose_kernel(const float* __restrict__ x1, const float* __restrict__ x2) {
    __shared__ float tile[32][33];
    int which = blockIdx.z & 1, b = blockIdx.z >> 1;
    const float* x = which ? x2 : x1;
    float* xt = which ? g_x2t : g_x1t;
    int dt = blockIdx.y, pt = blockIdx.x;
    int tx = threadIdx.x, ty = threadIdx.y;            // 32 x 8
    const float* src = x + (size_t)b * 131072 + (size_t)(dt * 32) * 1024 + pt * 32;
    #pragma unroll
    for (int r = ty; r < 32; r += 8)
        tile[r][tx] = src[(size_t)r * 1024 + tx];
    __syncthreads();
    float* dst = xt + (size_t)(b * 1024 + pt * 32) * DDIM + dt * 32;
    #pragma unroll
    for (int r = ty; r < 32; r += 8)
        dst[(size_t)r * DDIM + tx] = tile[tx][r];
}

// ---------------- K1: per-row norms + positive term (exact fp32) ----------------
__global__ void stats_kernel() {
    int warp = threadIdx.x >> 5, lane = threadIdx.x & 31;
    int row = blockIdx.x * 8 + warp;
    const float4* r1 = (const float4*)(g_x1t + (size_t)row * DDIM);
    const float4* r2 = (const float4*)(g_x2t + (size_t)row * DDIM);
    float4 a = r1[lane], b = r2[lane];
    float s1 = a.x*a.x + a.y*a.y + a.z*a.z + a.w*a.w;
    float s2 = b.x*b.x + b.y*b.y + b.z*b.z + b.w*b.w;
    #pragma unroll
    for (int o = 16; o > 0; o >>= 1) {
        s1 += __shfl_xor_sync(0xffffffffu, s1, o);
        s2 += __shfl_xor_sync(0xffffffffu, s2, o);
    }
    float in1 = 1.0f / fmaxf(sqrtf(s1), 1e-12f);
    float in2 = 1.0f / fmaxf(sqrtf(s2), 1e-12f);
    float sc = in1 * in2 * INV_TEMP;
    float p = expf(a.x*b.x*sc) + expf(a.y*b.y*sc) + expf(a.z*b.z*sc) + expf(a.w*b.w*sc);
    #pragma unroll
    for (int o = 16; o > 0; o >>= 1) p += __shfl_xor_sync(0xffffffffu, p, o);
    if (lane == 0) { g_sq[row] = s1; g_invn[row] = in1; g_pos[row] = p; }
}

// ---------------- K2: tf32 mma Gram, upper-triangle; epilogue emits fp16 KEYS ----------------
__device__ __forceinline__ void mma_tf32(float c[4], const unsigned a[4], const unsigned b[2]) {
    asm volatile(
        "mma.sync.aligned.m16n8k8.row.col.f32.tf32.tf32.f32 "
        "{%0,%1,%2,%3}, {%4,%5,%6,%7}, {%8,%9}, {%0,%1,%2,%3};\n"
        : "+f"(c[0]), "+f"(c[1]), "+f"(c[2]), "+f"(c[3])
        : "r"(a[0]), "r"(a[1]), "r"(a[2]), "r"(a[3]), "r"(b[0]), "r"(b[1]));
}

__global__ __launch_bounds__(512, 1) void gemm_tc_kernel() {
    extern __shared__ float sm[];
    float* As = sm;                      // [128][TPAD]
    float* Bs = sm + 128 * TPAD;
    __shared__ float sqA[128], sqB[128];
    const float* A = g_x1t;

    int t = blockIdx.x;
    int bi = 0;
    while (t >= NTILE - bi) { t -= NTILE - bi; bi++; }
    int bj = bi + t;
    int bm = bi * 128, bn = bj * 128;

    int tid = threadIdx.x;
    int wid = tid >> 5, lane = tid & 31;
    int wm = wid >> 2, wn = wid & 3;
    int g = lane >> 2, tg = lane & 3;

    if (tid < 128) sqA[tid] = g_sq[bm + tid];
    else if (tid < 256) sqB[tid - 128] = g_sq[bn + tid - 128];

    unsigned sA = (unsigned)__cvta_generic_to_shared(As);
    unsigned sB = (unsigned)__cvta_generic_to_shared(Bs);

    #pragma unroll
    for (int c = 0; c < 4; c++) {
        int k0 = c * 32;
        #pragma unroll
        for (int tt = 0; tt < 2; tt++) {
            int idx = tid + tt * 512;
            int r  = idx >> 3;
            int kk = (idx & 7) << 2;
            const float* ga = A + (size_t)(bm + r) * DDIM + k0 + kk;
            unsigned da = sA + (unsigned)(r * TPAD + k0 + kk) * 4u;
            asm volatile("cp.async.ca.shared.global [%0], [%1], 16;" :: "r"(da), "l"(ga));
            const float* gb = A + (size_t)(bn + r) * DDIM + k0 + kk;
            unsigned db = sB + (unsigned)(r * TPAD + k0 + kk) * 4u;
            asm volatile("cp.async.ca.shared.global [%0], [%1], 16;" :: "r"(db), "l"(gb));
        }
        asm volatile("cp.async.commit_group;");
    }

    float acc[2][4][4];
    #pragma unroll
    for (int mt = 0; mt < 2; mt++)
        #pragma unroll
        for (int nt = 0; nt < 4; nt++)
            #pragma unroll
            for (int q = 0; q < 4; q++) acc[mt][nt][q] = 0.0f;

    #pragma unroll
    for (int ch = 0; ch < 4; ch++) {
        if      (ch == 0) asm volatile("cp.async.wait_group 3;");
        else if (ch == 1) asm volatile("cp.async.wait_group 2;");
        else if (ch == 2) asm volatile("cp.async.wait_group 1;");
        else              asm volatile("cp.async.wait_group 0;");
        __syncthreads();
        #pragma unroll
        for (int kk = 0; kk < 4; kk++) {
            int kb = ch * 32 + kk * 8;
            unsigned a[2][4], b[4][2];
            #pragma unroll
            for (int mt = 0; mt < 2; mt++) {
                int r0 = wm * 32 + mt * 16;
                a[mt][0] = __float_as_uint(As[(r0 + g    ) * TPAD + kb + tg]);
                a[mt][1] = __float_as_uint(As[(r0 + g + 8) * TPAD + kb + tg]);
                a[mt][2] = __float_as_uint(As[(r0 + g    ) * TPAD + kb + tg + 4]);
                a[mt][3] = __float_as_uint(As[(r0 + g + 8) * TPAD + kb + tg + 4]);
            }
            #pragma unroll
            for (int nt = 0; nt < 4; nt++) {
                int rb = wn * 32 + nt * 8 + g;
                b[nt][0] = __float_as_uint(Bs[rb * TPAD + kb + tg]);
                b[nt][1] = __float_as_uint(Bs[rb * TPAD + kb + tg + 4]);
            }
            #pragma unroll
            for (int mt = 0; mt < 2; mt++)
                #pragma unroll
                for (int nt = 0; nt < 4; nt++)
                    mma_tf32(acc[mt][nt], a[mt], b[nt]);
        }
    }

    // direct tile (bm, bn): key = sq[col] - 2*dot, fp16
    #pragma unroll
    for (int mt = 0; mt < 2; mt++) {
        #pragma unroll
        for (int nt = 0; nt < 4; nt++) {
            int lr = wm * 32 + mt * 16 + g;
            int lc = wn * 32 + nt * 8 + tg * 2;
            float k0 = sqB[lc]     - 2.0f * acc[mt][nt][0];
            float k1 = sqB[lc + 1] - 2.0f * acc[mt][nt][1];
            float k2 = sqB[lc]     - 2.0f * acc[mt][nt][2];
            float k3 = sqB[lc + 1] - 2.0f * acc[mt][nt][3];
            *(__half2*)(g_key + (size_t)(bm + lr) * NROWS + bn + lc) =
                __floats2half2_rn(k0, k1);
            *(__half2*)(g_key + (size_t)(bm + lr + 8) * NROWS + bn + lc) =
                __floats2half2_rn(k2, k3);
        }
    }

    // mirrored tile (bn, bm)
    if (bi != bj) {
        __syncthreads();
        __half* Cth = (__half*)sm;       // [128 rows (bn-local)][MPAD]
        #pragma unroll
        for (int mt = 0; mt < 2; mt++) {
            #pragma unroll
            for (int nt = 0; nt < 4; nt++) {
                int r = wm * 32 + mt * 16 + g;
                int c = wn * 32 + nt * 8 + tg * 2;
                Cth[(c    ) * MPAD + r    ] = __float2half_rn(sqA[r]     - 2.0f * acc[mt][nt][0]);
                Cth[(c + 1) * MPAD + r    ] = __float2half_rn(sqA[r]     - 2.0f * acc[mt][nt][1]);
                Cth[(c    ) * MPAD + r + 8] = __float2half_rn(sqA[r + 8] - 2.0f * acc[mt][nt][2]);
                Cth[(c + 1) * MPAD + r + 8] = __float2half_rn(sqA[r + 8] - 2.0f * acc[mt][nt][3]);
            }
        }
        __syncthreads();
        #pragma unroll
        for (int it = 0; it < 4; it++) {
            int idx8 = it * 512 + tid;
            int rT = idx8 >> 4, c8 = (idx8 & 15) << 3;
            uint4 v = *(const uint4*)(Cth + rT * MPAD + c8);
            *(uint4*)(g_key + (size_t)(bn + rT) * NROWS + bm + c8) = v;
        }
    }
}

// ---------------- K3: 16-bit radix candidate select + exact fp32 re-rank ----------------
// key[l] (l = v*8 + s) corresponds to column j = tid*8 + v*2048 + s.
__device__ __forceinline__ int key_index(int tid, int l) {
    return tid * 8 + ((l >> 3) << 11) + (l & 7);
}
__device__ __forceinline__ unsigned ord16(unsigned h) {   // order-preserving fp16->u16
    return (h & 0x8000u) ? (~h & 0xFFFFu) : (h | 0x8000u);
}

__global__ __launch_bounds__(256, 4) void select_kernel() {
    int i = blockIdx.x;
    int tid = threadIdx.x, lane = tid & 31, wid = tid >> 5;
    const uint4* krow = (const uint4*)(g_key + (size_t)i * NROWS);  // 1024 uint4

    __shared__ unsigned histc[NHIST][HPAD];      // copy = wid*4 + (lane&3)
    __shared__ unsigned s_wsum[8];
    __shared__ unsigned s_bin, s_above, s_n;
    __shared__ __align__(16) float srow[DDIM];
    __shared__ int      s_cand[CAP];
    __shared__ __align__(16) float s_keyv[CAP + 4];
    __shared__ float    s_dotc[CAP];
    __shared__ float    sacc[8];

    if (tid < 32)
        ((float4*)srow)[tid] = ((const float4*)(g_x1t + (size_t)i * DDIM))[tid];

    unsigned key[32];                                    // ordered u16 keys
    #pragma unroll
    for (int v = 0; v < 4; v++) {
        uint4 q = krow[tid + v * 256];
        unsigned w[4] = { q.x, q.y, q.z, q.w };
        #pragma unroll
        for (int wi = 0; wi < 4; wi++) {
            key[v * 8 + wi * 2    ] = ord16(w[wi] & 0xFFFFu);
            key[v * 8 + wi * 2 + 1] = ord16(w[wi] >> 16);
        }
    }

    // ---- 2-pass radix select (32 hist copies): exact RSEL-th largest u16 key ----
    unsigned mask = 0u, val = 0u;
    unsigned rank = RSEL;
    #pragma unroll
    for (int pass = 0; pass < 2; pass++) {
        int shift = 8 - pass * 8;
        for (int e = tid; e < NHIST * HPAD; e += 256)
            ((unsigned*)histc)[e] = 0u;
        __syncthreads();
        unsigned* myhist = histc[wid * 4 + (lane & 3)];
        #pragma unroll
        for (int l = 0; l < 32; l++) {
            unsigned k = key[l];
            if ((k & mask) == val)
                atomicAdd(&myhist[(k >> shift) & 255u], 1u);
        }
        __syncthreads();
        unsigned c = 0;                          // thread t owns bin (255-t); merge copies
        #pragma unroll
        for (int w = 0; w < NHIST; w++) c += histc[w][255 - tid];
        unsigned v = c;
        #pragma unroll
        for (int o = 1; o < 32; o <<= 1) {
            unsigned u = __shfl_up_sync(0xffffffffu, v, o);
            if (lane >= o) v += u;
        }
        if (lane == 31) s_wsum[wid] = v;
        __syncthreads();
        unsigned off = 0;
        for (int w = 0; w < wid; w++) off += s_wsum[w];
        v += off;
        if (v >= rank && (v - c) < rank) {       // unique boundary thread
            s_bin = (unsigned)(255 - tid);
            s_above = v - c;
        }
        __syncthreads();
        val  |= s_bin << shift;
        mask |= 0xFFu << shift;
        rank -= s_above;
        __syncthreads();
    }
    unsigned thr = val;

    // ---- deterministic compaction of candidate indices (scan, no atomics) ----
    unsigned myc = 0;
    #pragma unroll
    for (int l = 0; l < 32; l++) myc += (key[l] >= thr);
    unsigned v = myc;
    #pragma unroll
    for (int o = 1; o < 32; o <<= 1) {
        unsigned u = __shfl_up_sync(0xffffffffu, v, o);
        if (lane >= o) v += u;
    }
    if (lane == 31) s_wsum[wid] = v;
    __syncthreads();
    unsigned off = 0;
    for (int w = 0; w < wid; w++) off += s_wsum[w];
    unsigned p = off + v - myc;                  // exclusive prefix
    #pragma unroll
    for (int l = 0; l < 32; l++) {
        if (key[l] >= thr) {
            if (p < CAP) s_cand[p] = key_index(tid, l);
            p++;
        }
    }
    if (tid == 255) s_n = (p < CAP) ? p : CAP;
    __syncthreads();
    int n = (int)s_n;

    // ---- exact fp32 dots: WARP per candidate (coalesced row reads, 4 wf/cand), 2-way ILP ----
    {
        float4 a4 = ((const float4*)srow)[lane];
        for (int c = wid * 2; c < n; c += 16) {
            int jA = s_cand[c];
            float4 bA = ((const float4*)(g_x1t + (size_t)jA * DDIM))[lane];
            float dA = a4.x*bA.x + a4.y*bA.y + a4.z*bA.z + a4.w*bA.w;
            int hasB = (c + 1 < n);
            float dB = 0.0f; int jB = 0;
            if (hasB) {
                jB = s_cand[c + 1];
                float4 bB = ((const float4*)(g_x1t + (size_t)jB * DDIM))[lane];
                dB = a4.x*bB.x + a4.y*bB.y + a4.z*bB.z + a4.w*bB.w;
            }
            #pragma unroll
            for (int o = 16; o > 0; o >>= 1) {
                dA += __shfl_xor_sync(0xffffffffu, dA, o);
                dB += __shfl_xor_sync(0xffffffffu, dB, o);
            }
            if (lane == 0) {
                s_dotc[c] = dA;
                s_keyv[c] = g_sq[jA] - 2.0f * dA;
                if (hasB) {
                    s_dotc[c + 1] = dB;
                    s_keyv[c + 1] = g_sq[jB] - 2.0f * dB;
                }
            }
        }
    }
    for (int c = n + tid; c < CAP + 4; c += 256)
        s_keyv[c] = -3.4e38f;                    // pad so float4 re-rank reads are inert
    __syncthreads();

    // ---- exact re-rank among candidates (vectorized, strict >); sum exp over top-100 ----
    float inv_i = g_invn[i];
    float acc = 0.0f;
    int n4 = (n + 3) >> 2;
    for (int c = tid; c < n; c += 256) {
        float kc = s_keyv[c];
        int greater = 0;
        for (int f4 = 0; f4 < n4; f4++) {
            float4 kf = ((const float4*)s_keyv)[f4];
            greater += (kf.x > kc) + (kf.y > kc) + (kf.z > kc) + (kf.w > kc);
        }
        if (greater < KNEG)
            acc += expf(s_dotc[c] * inv_i * g_invn[s_cand[c]] * INV_TEMP);
    }
    #pragma unroll
    for (int o = 16; o > 0; o >>= 1) acc += __shfl_xor_sync(0xffffffffu, acc, o);
    if (lane == 0) sacc[wid] = acc;
    __syncthreads();
    if (tid == 0) {
        float t = 0.0f;
        for (int w = 0; w < 8; w++) t += sacc[w];
        g_loss[i] = log1pf(t / g_pos[i]);        // log(P+N) - log(P)
    }
}

// ---------------- K4: deterministic mean ----------------
__global__ void reduce_kernel(float* __restrict__ out) {
    __shared__ float s[256];
    float a = 0.0f;
    for (int j = threadIdx.x; j < NROWS; j += 256) a += g_loss[j];
    s[threadIdx.x] = a;
    __syncthreads();
    for (int st = 128; st > 0; st >>= 1) {
        if (threadIdx.x < st) s[threadIdx.x] += s[threadIdx.x + st];
        __syncthreads();
    }
    if (threadIdx.x == 0) out[0] = s[0] * (1.0f / NROWS);
}

// ---------------- launch ----------------
extern "C" void kernel_launch(void* const* d_in, const int* in_sizes, int n_in,
                              void* d_out, int out_size) {
    const float* x1 = (const float*)d_in[0];
    const float* x2 = (const float*)d_in[1];
    float* out = (float*)d_out;

    cudaFuncSetAttribute(gemm_tc_kernel,
                         cudaFuncAttributeMaxDynamicSharedMemorySize, GEMM_SMEM);

    dim3 tgrid(32, 4, 16), tblk(32, 8);      // z = batch*2 + which
    transpose_kernel<<<tgrid, tblk>>>(x1, x2);
    stats_kernel<<<NROWS / 8, 256>>>();
    gemm_tc_kernel<<<NTRI, 512, GEMM_SMEM>>>();
    select_kernel<<<NROWS, 256>>>();
    reduce_kernel<<<1, 256>>>(out);
}

// round 17
// speedup vs baseline: 1.1084x; 1.0596x over previous
#include <cuda_runtime.h>
#include <cuda_fp16.h>
#include <math.h>

#define NROWS 8192
#define DDIM  128
#define KNEG  100
#define RSEL  160          // candidate superset rank (slack for tf32+fp16 key noise)
#define CAP   320          // candidate buffer capacity
#define INV_TEMP (1.0f/0.07f)
#define TPAD 132
#define MPAD 136           // half-precision mirror staging stride
#define GEMM_SMEM (2 * 128 * TPAD * 4)
#define NTILE 64
#define NTRI  (NTILE * (NTILE + 1) / 2)   // 2080 upper-triangular tiles
#define HPAD 257           // histogram copy stride
#define NHIST 32           // histogram copies (atomic conflict dilution)

// ---------------- scratch (device globals: allowed). 16B-aligned for vector ld/st ----
__device__ __align__(16) float  g_x1t[NROWS * DDIM];          // transposed x1 (8192 x 128)
__device__ __align__(16) float  g_x2t[NROWS * DDIM];          // transposed x2
__device__ float g_sq [NROWS];                                // |x1_i|^2
__device__ float g_invn[NROWS];                               // 1/|x1_i|
__device__ float g_pos[NROWS];                                // positive sums
__device__ __align__(16) __half g_key[(size_t)NROWS * NROWS]; // fp16 selection keys (128 MB)
__device__ float g_loss[NROWS];

// ---------------- K0: transpose (b,d,h,w) -> (b*h*w, d); both tensors in one launch ----
__global__ void transpose_kernel(const float* __restrict__ x1, const float* __restrict__ x2) {
    __shared__ float tile[32][33];
    int which = blockIdx.z & 1, b = blockIdx.z >> 1;
    const float* x = which ? x2 : x1;
    float* xt = which ? g_x2t : g_x1t;
    int dt = blockIdx.y, pt = blockIdx.x;
    int tx = threadIdx.x, ty = threadIdx.y;            // 32 x 8
    const float* src = x + (size_t)b * 131072 + (size_t)(dt * 32) * 1024 + pt * 32;
    #pragma unroll
    for (int r = ty; r < 32; r += 8)
        tile[r][tx] = src[(size_t)r * 1024 + tx];
    __syncthreads();
    float* dst = xt + (size_t)(b * 1024 + pt * 32) * DDIM + dt * 32;
    #pragma unroll
    for (int r = ty; r < 32; r += 8)
        dst[(size_t)r * DDIM + tx] = tile[tx][r];
}

// ---------------- K1: per-row norms + positive term (exact fp32) ----------------
__global__ void stats_kernel() {
    int warp = threadIdx.x >> 5, lane = threadIdx.x & 31;
    int row = blockIdx.x * 8 + warp;
    const float4* r1 = (const float4*)(g_x1t + (size_t)row * DDIM);
    const float4* r2 = (const float4*)(g_x2t + (size_t)row * DDIM);
    float4 a = r1[lane], b = r2[lane];
    float s1 = a.x*a.x + a.y*a.y + a.z*a.z + a.w*a.w;
    float s2 = b.x*b.x + b.y*b.y + b.z*b.z + b.w*b.w;
    #pragma unroll
    for (int o = 16; o > 0; o >>= 1) {
        s1 += __shfl_xor_sync(0xffffffffu, s1, o);
        s2 += __shfl_xor_sync(0xffffffffu, s2, o);
    }
    float in1 = 1.0f / fmaxf(sqrtf(s1), 1e-12f);
    float in2 = 1.0f / fmaxf(sqrtf(s2), 1e-12f);
    float sc = in1 * in2 * INV_TEMP;
    float p = expf(a.x*b.x*sc) + expf(a.y*b.y*sc) + expf(a.z*b.z*sc) + expf(a.w*b.w*sc);
    #pragma unroll
    for (int o = 16; o > 0; o >>= 1) p += __shfl_xor_sync(0xffffffffu, p, o);
    if (lane == 0) { g_sq[row] = s1; g_invn[row] = in1; g_pos[row] = p; }
}

// ---------------- K2: tf32 mma Gram, upper-triangle; epilogue emits fp16 KEYS ----------------
__device__ __forceinline__ void mma_tf32(float c[4], const unsigned a[4], const unsigned b[2]) {
    asm volatile(
        "mma.sync.aligned.m16n8k8.row.col.f32.tf32.tf32.f32 "
        "{%0,%1,%2,%3}, {%4,%5,%6,%7}, {%8,%9}, {%0,%1,%2,%3};\n"
        : "+f"(c[0]), "+f"(c[1]), "+f"(c[2]), "+f"(c[3])
        : "r"(a[0]), "r"(a[1]), "r"(a[2]), "r"(a[3]), "r"(b[0]), "r"(b[1]));
}

__global__ __launch_bounds__(512, 1) void gemm_tc_kernel() {
    extern __shared__ float sm[];
    float* As = sm;                      // [128][TPAD]
    float* Bs = sm + 128 * TPAD;
    __shared__ float sqA[128], sqB[128];
    const float* A = g_x1t;

    int t = blockIdx.x;
    int bi = 0;
    while (t >= NTILE - bi) { t -= NTILE - bi; bi++; }
    int bj = bi + t;
    int bm = bi * 128, bn = bj * 128;

    int tid = threadIdx.x;
    int wid = tid >> 5, lane = tid & 31;
    int wm = wid >> 2, wn = wid & 3;
    int g = lane >> 2, tg = lane & 3;

    if (tid < 128) sqA[tid] = g_sq[bm + tid];
    else if (tid < 256) sqB[tid - 128] = g_sq[bn + tid - 128];

    unsigned sA = (unsigned)__cvta_generic_to_shared(As);
    unsigned sB = (unsigned)__cvta_generic_to_shared(Bs);

    #pragma unroll
    for (int c = 0; c < 4; c++) {
        int k0 = c * 32;
        #pragma unroll
        for (int tt = 0; tt < 2; tt++) {
            int idx = tid + tt * 512;
            int r  = idx >> 3;
            int kk = (idx & 7) << 2;
            const float* ga = A + (size_t)(bm + r) * DDIM + k0 + kk;
            unsigned da = sA + (unsigned)(r * TPAD + k0 + kk) * 4u;
            asm volatile("cp.async.ca.shared.global [%0], [%1], 16;" :: "r"(da), "l"(ga));
            const float* gb = A + (size_t)(bn + r) * DDIM + k0 + kk;
            unsigned db = sB + (unsigned)(r * TPAD + k0 + kk) * 4u;
            asm volatile("cp.async.ca.shared.global [%0], [%1], 16;" :: "r"(db), "l"(gb));
        }
        asm volatile("cp.async.commit_group;");
    }

    float acc[2][4][4];
    #pragma unroll
    for (int mt = 0; mt < 2; mt++)
        #pragma unroll
        for (int nt = 0; nt < 4; nt++)
            #pragma unroll
            for (int q = 0; q < 4; q++) acc[mt][nt][q] = 0.0f;

    #pragma unroll
    for (int ch = 0; ch < 4; ch++) {
        if      (ch == 0) asm volatile("cp.async.wait_group 3;");
        else if (ch == 1) asm volatile("cp.async.wait_group 2;");
        else if (ch == 2) asm volatile("cp.async.wait_group 1;");
        else              asm volatile("cp.async.wait_group 0;");
        __syncthreads();
        #pragma unroll
        for (int kk = 0; kk < 4; kk++) {
            int kb = ch * 32 + kk * 8;
            unsigned a[2][4], b[4][2];
            #pragma unroll
            for (int mt = 0; mt < 2; mt++) {
                int r0 = wm * 32 + mt * 16;
                a[mt][0] = __float_as_uint(As[(r0 + g    ) * TPAD + kb + tg]);
                a[mt][1] = __float_as_uint(As[(r0 + g + 8) * TPAD + kb + tg]);
                a[mt][2] = __float_as_uint(As[(r0 + g    ) * TPAD + kb + tg + 4]);
                a[mt][3] = __float_as_uint(As[(r0 + g + 8) * TPAD + kb + tg + 4]);
            }
            #pragma unroll
            for (int nt = 0; nt < 4; nt++) {
                int rb = wn * 32 + nt * 8 + g;
                b[nt][0] = __float_as_uint(Bs[rb * TPAD + kb + tg]);
                b[nt][1] = __float_as_uint(Bs[rb * TPAD + kb + tg + 4]);
            }
            #pragma unroll
            for (int mt = 0; mt < 2; mt++)
                #pragma unroll
                for (int nt = 0; nt < 4; nt++)
                    mma_tf32(acc[mt][nt], a[mt], b[nt]);
        }
    }

    // direct tile (bm, bn): key = sq[col] - 2*dot, fp16
    #pragma unroll
    for (int mt = 0; mt < 2; mt++) {
        #pragma unroll
        for (int nt = 0; nt < 4; nt++) {
            int lr = wm * 32 + mt * 16 + g;
            int lc = wn * 32 + nt * 8 + tg * 2;
            float k0 = sqB[lc]     - 2.0f * acc[mt][nt][0];
            float k1 = sqB[lc + 1] - 2.0f * acc[mt][nt][1];
            float k2 = sqB[lc]     - 2.0f * acc[mt][nt][2];
            float k3 = sqB[lc + 1] - 2.0f * acc[mt][nt][3];
            *(__half2*)(g_key + (size_t)(bm + lr) * NROWS + bn + lc) =
                __floats2half2_rn(k0, k1);
            *(__half2*)(g_key + (size_t)(bm + lr + 8) * NROWS + bn + lc) =
                __floats2half2_rn(k2, k3);
        }
    }

    // mirrored tile (bn, bm)
    if (bi != bj) {
        __syncthreads();
        __half* Cth = (__half*)sm;       // [128 rows (bn-local)][MPAD]
        #pragma unroll
        for (int mt = 0; mt < 2; mt++) {
            #pragma unroll
            for (int nt = 0; nt < 4; nt++) {
                int r = wm * 32 + mt * 16 + g;
                int c = wn * 32 + nt * 8 + tg * 2;
                Cth[(c    ) * MPAD + r    ] = __float2half_rn(sqA[r]     - 2.0f * acc[mt][nt][0]);
                Cth[(c + 1) * MPAD + r    ] = __float2half_rn(sqA[r]     - 2.0f * acc[mt][nt][1]);
                Cth[(c    ) * MPAD + r + 8] = __float2half_rn(sqA[r + 8] - 2.0f * acc[mt][nt][2]);
                Cth[(c + 1) * MPAD + r + 8] = __float2half_rn(sqA[r + 8] - 2.0f * acc[mt][nt][3]);
            }
        }
        __syncthreads();
        #pragma unroll
        for (int it = 0; it < 4; it++) {
            int idx8 = it * 512 + tid;
            int rT = idx8 >> 4, c8 = (idx8 & 15) << 3;
            uint4 v = *(const uint4*)(Cth + rT * MPAD + c8);
            *(uint4*)(g_key + (size_t)(bn + rT) * NROWS + bm + c8) = v;
        }
    }
}

// ---------------- K3: 16-bit radix candidate select + exact fp32 re-rank ----------------
// Keys kept PACKED (16 u32 regs of ordered-u16 pairs). Packed reg r holds keys
// l = 2r (lo half) and l = 2r+1 (hi half); column j = tid*8 + (r>>2)*2048 + (r&3)*2 + h.
__device__ __forceinline__ int key_index_rh(int tid, int r, int h) {
    return tid * 8 + ((r >> 2) << 11) + ((r & 3) << 1) + h;
}
// SIMD order-preserving fp16x2 -> u16x2: per half, neg ? ~u : u|0x8000
__device__ __forceinline__ unsigned ordpair(unsigned q) {
    unsigned t = (q >> 15) & 0x00010001u;
    unsigned m = 0x80008000u | (t * 0x7FFFu);
    return q ^ m;
}

__global__ __launch_bounds__(256, 5) void select_kernel() {
    int i = blockIdx.x;
    int tid = threadIdx.x, lane = tid & 31, wid = tid >> 5;
    const uint4* krow = (const uint4*)(g_key + (size_t)i * NROWS);  // 1024 uint4

    __shared__ __align__(16) unsigned histc[NHIST][HPAD];  // copy = wid*4 + (lane&3)
    __shared__ unsigned s_wsum[8];
    __shared__ unsigned s_bin, s_above, s_n;
    __shared__ __align__(16) float srow[DDIM];
    __shared__ int      s_cand[CAP];
    __shared__ __align__(16) float s_keyv[CAP + 4];
    __shared__ float    s_dotc[CAP];
    __shared__ float    sacc[8];

    if (tid < 32)
        ((float4*)srow)[tid] = ((const float4*)(g_x1t + (size_t)i * DDIM))[tid];

    unsigned kp[16];                                     // packed ordered u16 keys
    #pragma unroll
    for (int v = 0; v < 4; v++) {
        uint4 q = krow[tid + v * 256];
        kp[v * 4 + 0] = ordpair(q.x);
        kp[v * 4 + 1] = ordpair(q.y);
        kp[v * 4 + 2] = ordpair(q.z);
        kp[v * 4 + 3] = ordpair(q.w);
    }

    // ---- 2-pass radix select (32 hist copies): exact RSEL-th largest u16 key ----
    unsigned mask = 0u, val = 0u;
    unsigned rank = RSEL;
    #pragma unroll
    for (int pass = 0; pass < 2; pass++) {
        int shift = 8 - pass * 8;
        // vectorized zero of the flat copy region (NHIST*HPAD = 8224 = 2056 uint4)
        for (int e = tid; e < (NHIST * HPAD) / 4; e += 256)
            ((uint4*)histc)[e] = make_uint4(0u, 0u, 0u, 0u);
        __syncthreads();
        unsigned* myhist = histc[wid * 4 + (lane & 3)];
        #pragma unroll
        for (int r = 0; r < 16; r++) {
            unsigned pair = kp[r];
            unsigned k0 = pair & 0xFFFFu, k1 = pair >> 16;
            if ((k0 & mask) == val) atomicAdd(&myhist[(k0 >> shift) & 255u], 1u);
            if ((k1 & mask) == val) atomicAdd(&myhist[(k1 >> shift) & 255u], 1u);
        }
        __syncthreads();
        unsigned c = 0;                          // thread t owns bin (255-t); merge copies
        #pragma unroll
        for (int w = 0; w < NHIST; w++) c += histc[w][255 - tid];
        unsigned v = c;
        #pragma unroll
        for (int o = 1; o < 32; o <<= 1) {
            unsigned u = __shfl_up_sync(0xffffffffu, v, o);
            if (lane >= o) v += u;
        }
        if (lane == 31) s_wsum[wid] = v;
        __syncthreads();
        unsigned off = 0;
        for (int w = 0; w < wid; w++) off += s_wsum[w];
        v += off;
        if (v >= rank && (v - c) < rank) {       // unique boundary thread
            s_bin = (unsigned)(255 - tid);
            s_above = v - c;
        }
        __syncthreads();
        val  |= s_bin << shift;
        mask |= 0xFFu << shift;
        rank -= s_above;
        __syncthreads();
    }
    unsigned thr = val;

    // ---- deterministic compaction of candidate indices (scan, no atomics) ----
    unsigned myc = 0;
    #pragma unroll
    for (int r = 0; r < 16; r++) {
        unsigned pair = kp[r];
        myc += ((pair & 0xFFFFu) >= thr) + ((pair >> 16) >= thr);
    }
    unsigned v = myc;
    #pragma unroll
    for (int o = 1; o < 32; o <<= 1) {
        unsigned u = __shfl_up_sync(0xffffffffu, v, o);
        if (lane >= o) v += u;
    }
    if (lane == 31) s_wsum[wid] = v;
    __syncthreads();
    unsigned off = 0;
    for (int w = 0; w < wid; w++) off += s_wsum[w];
    unsigned p = off + v - myc;                  // exclusive prefix
    #pragma unroll
    for (int r = 0; r < 16; r++) {
        unsigned pair = kp[r];
        if ((pair & 0xFFFFu) >= thr) {
            if (p < CAP) s_cand[p] = key_index_rh(tid, r, 0);
            p++;
        }
        if ((pair >> 16) >= thr) {
            if (p < CAP) s_cand[p] = key_index_rh(tid, r, 1);
            p++;
        }
    }
    if (tid == 255) s_n = (p < CAP) ? p : CAP;
    __syncthreads();
    int n = (int)s_n;

    // ---- exact fp32 dots: WARP per candidate (coalesced row reads), 2-way ILP ----
    {
        float4 a4 = ((const float4*)srow)[lane];
        for (int c = wid * 2; c < n; c += 16) {
            int jA = s_cand[c];
            float4 bA = ((const float4*)(g_x1t + (size_t)jA * DDIM))[lane];
            float dA = a4.x*bA.x + a4.y*bA.y + a4.z*bA.z + a4.w*bA.w;
            int hasB = (c + 1 < n);
            float dB = 0.0f; int jB = 0;
            if (hasB) {
                jB = s_cand[c + 1];
                float4 bB = ((const float4*)(g_x1t + (size_t)jB * DDIM))[lane];
                dB = a4.x*bB.x + a4.y*bB.y + a4.z*bB.z + a4.w*bB.w;
            }
            #pragma unroll
            for (int o = 16; o > 0; o >>= 1) {
                dA += __shfl_xor_sync(0xffffffffu, dA, o);
                dB += __shfl_xor_sync(0xffffffffu, dB, o);
            }
            if (lane == 0) {
                s_dotc[c] = dA;
                s_keyv[c] = g_sq[jA] - 2.0f * dA;
                if (hasB) {
                    s_dotc[c + 1] = dB;
                    s_keyv[c + 1] = g_sq[jB] - 2.0f * dB;
                }
            }
        }
    }
    for (int c = n + tid; c < CAP + 4; c += 256)
        s_keyv[c] = -3.4e38f;                    // pad so float4 re-rank reads are inert
    __syncthreads();

    // ---- exact re-rank among candidates (vectorized, strict >); sum exp over top-100 ----
    float inv_i = g_invn[i];
    float acc = 0.0f;
    int n4 = (n + 3) >> 2;
    for (int c = tid; c < n; c += 256) {
        float kc = s_keyv[c];
        int greater = 0;
        for (int f4 = 0; f4 < n4; f4++) {
            float4 kf = ((const float4*)s_keyv)[f4];
            greater += (kf.x > kc) + (kf.y > kc) + (kf.z > kc) + (kf.w > kc);
        }
        if (greater < KNEG)
            acc += expf(s_dotc[c] * inv_i * g_invn[s_cand[c]] * INV_TEMP);
    }
    #pragma unroll
    for (int o = 16; o > 0; o >>= 1) acc += __shfl_xor_sync(0xffffffffu, acc, o);
    if (lane == 0) sacc[wid] = acc;
    __syncthreads();
    if (tid == 0) {
        float t = 0.0f;
        for (int w = 0; w < 8; w++) t += sacc[w];
        g_loss[i] = log1pf(t / g_pos[i]);        // log(P+N) - log(P)
    }
}

// ---------------- K4: deterministic mean ----------------
__global__ void reduce_kernel(float* __restrict__ out) {
    __shared__ float s[256];
    float a = 0.0f;
    for (int j = threadIdx.x; j < NROWS; j += 256) a += g_loss[j];
    s[threadIdx.x] = a;
    __syncthreads();
    for (int st = 128; st > 0; st >>= 1) {
        if (threadIdx.x < st) s[threadIdx.x] += s[threadIdx.x + st];
        __syncthreads();
    }
    if (threadIdx.x == 0) out[0] = s[0] * (1.0f / NROWS);
}

// ---------------- launch ----------------
extern "C" void kernel_launch(void* const* d_in, const int* in_sizes, int n_in,
                              void* d_out, int out_size) {
    const float* x1 = (const float*)d_in[0];
    const float* x2 = (const float*)d_in[1];
    float* out = (float*)d_out;

    cudaFuncSetAttribute(gemm_tc_kernel,
                         cudaFuncAttributeMaxDynamicSharedMemorySize, GEMM_SMEM);

    dim3 tgrid(32, 4, 16), tblk(32, 8);      // z = batch*2 + which
    transpose_kernel<<<tgrid, tblk>>>(x1, x2);
    stats_kernel<<<NROWS / 8, 256>>>();
    gemm_tc_kernel<<<NTRI, 512, GEMM_SMEM>>>();
    select_kernel<<<NROWS, 256>>>();
    reduce_kernel<<<1, 256>>>(out);
}